// round 1
// baseline (speedup 1.0000x reference)
#include <cuda_runtime.h>

#define D 256
#define BATCH 8
#define SEQ 1024
#define ROWS (BATCH*SEQ)
#define RT 32

// Scratch (static device globals -- no allocation allowed)
__device__ float g_MT[2][D*D];   // M transposed: MT[k][i] = M[i][k]
__device__ float g_PT[2][D*D];   // P transposed: PT[j][i] = P[i][j]
__device__ float g_xt[ROWS*D];   // post GEMM+LN activations
__device__ float g_y[ROWS*D];    // layer-1 output

// ---------------------------------------------------------------------------
// Transpose prep: M1,P1,M2,P2 (256x256 each) -> g_MT/g_PT, coalesced both ways
// ---------------------------------------------------------------------------
__global__ void transpose_kernel(const float* __restrict__ M1, const float* __restrict__ P1,
                                 const float* __restrict__ M2, const float* __restrict__ P2)
{
    __shared__ float tile[32][33];
    const float* src; float* dst;
    int z = blockIdx.z;
    if      (z == 0) { src = M1; dst = g_MT[0]; }
    else if (z == 1) { src = P1; dst = g_PT[0]; }
    else if (z == 2) { src = M2; dst = g_MT[1]; }
    else             { src = P2; dst = g_PT[1]; }

    int x = blockIdx.x * 32 + threadIdx.x;
    int y = blockIdx.y * 32 + threadIdx.y;
    #pragma unroll
    for (int r = 0; r < 32; r += 8)
        tile[threadIdx.y + r][threadIdx.x] = src[(y + r) * D + x];
    __syncthreads();
    x = blockIdx.y * 32 + threadIdx.x;
    y = blockIdx.x * 32 + threadIdx.y;
    #pragma unroll
    for (int r = 0; r < 32; r += 8)
        dst[(y + r) * D + x] = tile[threadIdx.x][threadIdx.y + r];
}

// ---------------------------------------------------------------------------
// Kernel A: g_xt = LayerNorm(X @ M^T) * g + b
// grid = ROWS/RT CTAs, 256 threads (thread = output column i), RT rows per CTA
// ---------------------------------------------------------------------------
__global__ __launch_bounds__(256)
void gemm_ln_kernel(const float* __restrict__ Xext, int layer,
                    const float* __restrict__ gw, const float* __restrict__ bw)
{
    // phase 1/2: xsT[k*36 + r]  (stride 36: keeps 16B alignment for LDS.128)
    // phase 3/4: xout[r*256 + i]
    __shared__ float sm[256 * 36];

    const float* X  = (layer == 0) ? Xext : g_y;
    const float* MT = g_MT[layer];
    float* XTout    = g_xt;

    const int tid = threadIdx.x;
    const int r0  = blockIdx.x * RT;

    // load X block [RT rows x 256 k], transposed into smem as [k][r]
    for (int idx = tid; idx < RT * D; idx += 256) {
        int r = idx >> 8, k = idx & 255;
        sm[k * 36 + r] = X[(r0 + r) * D + k];
    }
    __syncthreads();

    float acc[RT];
    #pragma unroll
    for (int r = 0; r < RT; r++) acc[r] = 0.f;

    const int i = tid;
    #pragma unroll 4
    for (int k = 0; k < D; k++) {
        float m = __ldg(&MT[k * D + i]);          // coalesced across warp
        #pragma unroll
        for (int r = 0; r < RT; r++)
            acc[r] = fmaf(sm[k * 36 + r], m, acc[r]);   // broadcast LDS
    }
    __syncthreads();

    // stash results as [r][i] for per-row LayerNorm
    #pragma unroll
    for (int r = 0; r < RT; r++) sm[r * D + i] = acc[r];
    __syncthreads();

    const int w = tid >> 5, lane = tid & 31;
    for (int rr = w; rr < RT; rr += 8) {
        float s1 = 0.f, s2 = 0.f;
        float v[8];
        #pragma unroll
        for (int u = 0; u < 8; u++) {
            v[u] = sm[rr * D + u * 32 + lane];
            s1 += v[u];
            s2 = fmaf(v[u], v[u], s2);
        }
        #pragma unroll
        for (int o = 16; o > 0; o >>= 1) {
            s1 += __shfl_xor_sync(0xffffffffu, s1, o);
            s2 += __shfl_xor_sync(0xffffffffu, s2, o);
        }
        float mu   = s1 * (1.0f / D);
        float var  = s2 * (1.0f / D) - mu * mu;
        float rstd = rsqrtf(var + 1e-5f);
        int row = r0 + rr;
        #pragma unroll
        for (int u = 0; u < 8; u++) {
            int col = u * 32 + lane;
            XTout[row * D + col] =
                (v[u] - mu) * rstd * __ldg(&gw[col]) + __ldg(&bw[col]);
        }
    }
}

// ---------------------------------------------------------------------------
// Kernel B: out[b,s,i] = res[b,s,i] + sum_j xt[b,s,j]*P[i,j]*cos(2*pi*s/(i*256+j+2))
// grid = SEQ CTAs (one per position s), 256 threads (thread = output dim i)
// ---------------------------------------------------------------------------
__global__ __launch_bounds__(256)
void phi_kernel(const float* __restrict__ resext, float* __restrict__ outext, int layer)
{
    __shared__ float xts[D * 8];   // [j][b]

    const float* XT  = g_xt;
    const float* PT  = g_PT[layer];
    const float* RES = (layer == 0) ? resext : g_y;
    float* OUT       = (layer == 0) ? g_y    : outext;

    const int s   = blockIdx.x;
    const int tid = threadIdx.x;

    // stage the 8 batch rows at position s, transposed -> [j][b]
    for (int idx = tid; idx < BATCH * D; idx += 256) {
        int b = idx >> 8, j = idx & 255;
        xts[j * 8 + b] = XT[((b << 10) + s) * D + j];
    }
    __syncthreads();

    float a0 = 0.f, a1 = 0.f, a2 = 0.f, a3 = 0.f;
    float a4 = 0.f, a5 = 0.f, a6 = 0.f, a7 = 0.f;

    const float sf = (float)s;
    float p = (float)(tid * D + 2);          // period, exact in fp32 (< 2^24)
    const float TWO_PI = 6.283185307179586f;

    #pragma unroll 4
    for (int j = 0; j < D; j++) {
        // t = s/p via rcp.approx + one Newton step; then frac(t) for range reduction
        float r;
        asm("rcp.approx.f32 %0, %1;" : "=f"(r) : "f"(p));
        float t = sf * r;
        t = fmaf(fmaf(-t, p, sf), r, t);
        t -= floorf(t);
        float c = __cosf(t * TWO_PI);
        float wv = c * __ldg(&PT[j * D + tid]);   // coalesced across warp

        const float* xb = &xts[j * 8];            // 32B aligned -> 2x LDS.128 broadcast
        a0 = fmaf(wv, xb[0], a0);
        a1 = fmaf(wv, xb[1], a1);
        a2 = fmaf(wv, xb[2], a2);
        a3 = fmaf(wv, xb[3], a3);
        a4 = fmaf(wv, xb[4], a4);
        a5 = fmaf(wv, xb[5], a5);
        a6 = fmaf(wv, xb[6], a6);
        a7 = fmaf(wv, xb[7], a7);
        p += 1.0f;
    }

    float acc[8] = {a0, a1, a2, a3, a4, a5, a6, a7};
    #pragma unroll
    for (int b = 0; b < 8; b++) {
        int off = ((b << 10) + s) * D + tid;
        OUT[off] = acc[b] + RES[off];
    }
}

// ---------------------------------------------------------------------------
extern "C" void kernel_launch(void* const* d_in, const int* in_sizes, int n_in,
                              void* d_out, int out_size)
{
    const float* seq = (const float*)d_in[0];
    const float* M1  = (const float*)d_in[1];
    const float* P1  = (const float*)d_in[2];
    const float* g1  = (const float*)d_in[3];
    const float* b1  = (const float*)d_in[4];
    const float* M2  = (const float*)d_in[5];
    const float* P2  = (const float*)d_in[6];
    const float* g2  = (const float*)d_in[7];
    const float* b2  = (const float*)d_in[8];
    float* out = (float*)d_out;

    transpose_kernel<<<dim3(8, 8, 4), dim3(32, 8)>>>(M1, P1, M2, P2);

    // layer 1
    gemm_ln_kernel<<<ROWS / RT, 256>>>(seq, 0, g1, b1);
    phi_kernel<<<SEQ, 256>>>(seq, nullptr, 0);

    // layer 2
    gemm_ln_kernel<<<ROWS / RT, 256>>>(nullptr, 1, g2, b2);
    phi_kernel<<<SEQ, 256>>>(nullptr, out, 1);
}

// round 4
// speedup vs baseline: 1.2664x; 1.2664x over previous
#include <cuda_runtime.h>

#define D 256
#define BATCH 8
#define SEQ 1024
#define ROWS (BATCH*SEQ)
#define RT 32
#define GS 4            // positions per phi CTA

typedef unsigned long long ull;

// Scratch (static device globals -- no allocation allowed)
__device__ float  g_MT[2][D*D];        // M transposed: MT[k][i] = M[i][k]
__device__ float2 g_tbl[2][D*D];       // tbl[l][j*256+i] = (P[i][j], 1/(i*256+j+2))
__device__ float  g_xt[ROWS*D];        // post GEMM+LN activations
__device__ float  g_y[ROWS*D];         // layer-1 output

// ---- f32x2 helpers (sm_103a packed fp32 pipe) ------------------------------
__device__ __forceinline__ ull pk2(float a, float b) {
    ull r; asm("mov.b64 %0, {%1,%2};" : "=l"(r) : "f"(a), "f"(b)); return r;
}
__device__ __forceinline__ void upk2(float& lo, float& hi, ull v) {
    asm("mov.b64 {%0,%1}, %2;" : "=f"(lo), "=f"(hi) : "l"(v));
}
__device__ __forceinline__ void fma2(ull& d, ull a, ull b) {
    asm("fma.rn.f32x2 %0, %1, %2, %0;" : "+l"(d) : "l"(a), "l"(b));
}

// ---------------------------------------------------------------------------
// Prep 1: transpose M1/M2 -> g_MT
// ---------------------------------------------------------------------------
__global__ void prep_mt_kernel(const float* __restrict__ M1, const float* __restrict__ M2)
{
    __shared__ float tile[32][33];
    const float* src = (blockIdx.z == 0) ? M1 : M2;
    float* dst = g_MT[blockIdx.z];

    int x = blockIdx.x * 32 + threadIdx.x;
    int y = blockIdx.y * 32 + threadIdx.y;
    #pragma unroll
    for (int r = 0; r < 32; r += 8)
        tile[threadIdx.y + r][threadIdx.x] = src[(y + r) * D + x];
    __syncthreads();
    x = blockIdx.y * 32 + threadIdx.x;
    y = blockIdx.x * 32 + threadIdx.y;
    #pragma unroll
    for (int r = 0; r < 32; r += 8)
        dst[(y + r) * D + x] = tile[threadIdx.x][threadIdx.y + r];
}

// ---------------------------------------------------------------------------
// Prep 2: fused table: g_tbl[l][j*256+i] = (P[i][j], 1/(i*256+j+2))
// ---------------------------------------------------------------------------
__global__ void prep_tbl_kernel(const float* __restrict__ P1, const float* __restrict__ P2)
{
    __shared__ float tile[32][33];
    const float* src = (blockIdx.z == 0) ? P1 : P2;
    float2* dst = g_tbl[blockIdx.z];

    int x = blockIdx.x * 32 + threadIdx.x;   // col j of P
    int y = blockIdx.y * 32 + threadIdx.y;   // row i of P
    #pragma unroll
    for (int r = 0; r < 32; r += 8)
        tile[threadIdx.y + r][threadIdx.x] = src[(y + r) * D + x];
    __syncthreads();
    int i = blockIdx.y * 32 + threadIdx.x;   // output col = i
    #pragma unroll
    for (int r = 0; r < 32; r += 8) {
        int j = blockIdx.x * 32 + threadIdx.y + r;
        float p = (float)(i * D + j + 2);    // exact in fp32 (< 2^24)
        dst[(j << 8) + i] = make_float2(tile[threadIdx.x][threadIdx.y + r], 1.0f / p);
    }
}

// ---------------------------------------------------------------------------
// Kernel A: g_xt = LayerNorm(X @ M^T) * g + b     (f32x2 mainloop)
// grid = ROWS/RT, 256 threads (thread = output column i), RT rows per CTA
// ---------------------------------------------------------------------------
__global__ __launch_bounds__(256)
void gemm_ln_kernel(const float* __restrict__ Xext, int layer,
                    const float* __restrict__ gw, const float* __restrict__ bw)
{
    // phase 1/2: x transposed [k][r], stride 36 floats (16B aligned rows)
    // phase 3/4: result [r][i]
    __shared__ float sm[256 * 36];

    const float* X  = (layer == 0) ? Xext : g_y;
    const float* MT = g_MT[layer];

    const int tid = threadIdx.x;
    const int r0  = blockIdx.x * RT;

    for (int idx = tid; idx < RT * D; idx += 256) {
        int r = idx >> 8, k = idx & 255;
        sm[k * 36 + r] = X[(r0 + r) * D + k];
    }
    __syncthreads();

    ull acc[16];
    #pragma unroll
    for (int q = 0; q < 16; q++) acc[q] = 0ULL;

    const int i = tid;
    #pragma unroll 4
    for (int k = 0; k < D; k++) {
        float m = __ldg(&MT[k * D + i]);                  // coalesced
        ull mm = pk2(m, m);
        const ulonglong2* xp = (const ulonglong2*)&sm[k * 36];   // 16B aligned, broadcast
        #pragma unroll
        for (int q = 0; q < 8; q++) {
            ulonglong2 v = xp[q];                         // rows 4q..4q+3
            fma2(acc[2 * q],     v.x, mm);
            fma2(acc[2 * q + 1], v.y, mm);
        }
    }
    __syncthreads();

    #pragma unroll
    for (int q = 0; q < 16; q++) {
        float lo, hi; upk2(lo, hi, acc[q]);
        sm[(2 * q) * D + i]     = lo;
        sm[(2 * q + 1) * D + i] = hi;
    }
    __syncthreads();

    const int w = tid >> 5, lane = tid & 31;
    for (int rr = w; rr < RT; rr += 8) {
        float s1 = 0.f, s2 = 0.f;
        float v[8];
        #pragma unroll
        for (int u = 0; u < 8; u++) {
            v[u] = sm[rr * D + u * 32 + lane];
            s1 += v[u];
            s2 = fmaf(v[u], v[u], s2);
        }
        #pragma unroll
        for (int o = 16; o > 0; o >>= 1) {
            s1 += __shfl_xor_sync(0xffffffffu, s1, o);
            s2 += __shfl_xor_sync(0xffffffffu, s2, o);
        }
        float mu   = s1 * (1.0f / D);
        float var  = s2 * (1.0f / D) - mu * mu;
        float rstd = rsqrtf(var + 1e-5f);
        int row = r0 + rr;
        #pragma unroll
        for (int u = 0; u < 8; u++) {
            int col = u * 32 + lane;
            g_xt[row * D + col] =
                (v[u] - mu) * rstd * __ldg(&gw[col]) + __ldg(&bw[col]);
        }
    }
}

// ---------------------------------------------------------------------------
// Kernel B: out[b,s,i] = res[b,s,i] + sum_j xt[b,s,j]*P[i,j]*cos(2*pi*s/per(i,j))
// grid = SEQ/GS CTAs (GS positions per CTA), 256 threads (thread = dim i)
// ---------------------------------------------------------------------------
__global__ __launch_bounds__(256)
void phi_kernel(const float* __restrict__ resext, float* __restrict__ outext, int layer)
{
    __shared__ float xts[GS * D * 8];   // [u][j][b]

    const float2* TB = g_tbl[layer];
    const float* RES = (layer == 0) ? resext : g_y;
    float* OUT       = (layer == 0) ? g_y    : outext;

    const int s0  = blockIdx.x * GS;
    const int tid = threadIdx.x;

    // stage GS*8 rows at positions s0..s0+GS-1, layout [u][j][b]
    for (int idx = tid; idx < GS * BATCH * D; idx += 256) {
        int row = idx >> 8;             // 0..31
        int j   = idx & 255;
        int b   = row >> 2;             // row = b*GS + u
        int u   = row & (GS - 1);
        xts[(u * D + j) * 8 + b] = g_xt[((b << 10) + s0 + u) * D + j];
    }
    __syncthreads();

    ull acc[GS][4];
    #pragma unroll
    for (int u = 0; u < GS; u++)
        #pragma unroll
        for (int q = 0; q < 4; q++) acc[u][q] = 0ULL;

    const float TWO_PI = 6.283185307179586f;
    float sf[GS];
    #pragma unroll
    for (int u = 0; u < GS; u++) sf[u] = (float)(s0 + u);

    #pragma unroll 2
    for (int j = 0; j < D; j++) {
        float2 pr = __ldg(&TB[(j << 8) + tid]);   // (P[i][j], 1/period) coalesced
        const float pt = pr.x, r = pr.y;
        #pragma unroll
        for (int u = 0; u < GS; u++) {
            float t = sf[u] * r;
            t -= floorf(t);                        // frac -> [0,1)
            float c = __cosf(t * TWO_PI);
            float wv = c * pt;
            ull wv2 = pk2(wv, wv);
            const ulonglong2* xb = (const ulonglong2*)&xts[(u * D + j) * 8];  // 32B aligned
            ulonglong2 x01 = xb[0];
            ulonglong2 x23 = xb[1];
            fma2(acc[u][0], x01.x, wv2);
            fma2(acc[u][1], x01.y, wv2);
            fma2(acc[u][2], x23.x, wv2);
            fma2(acc[u][3], x23.y, wv2);
        }
    }

    #pragma unroll
    for (int u = 0; u < GS; u++) {
        #pragma unroll
        for (int q = 0; q < 4; q++) {
            float lo, hi; upk2(lo, hi, acc[u][q]);
            int b0 = 2 * q;
            int off0 = ((b0 << 10)       + s0 + u) * D + tid;
            int off1 = (((b0 + 1) << 10) + s0 + u) * D + tid;
            OUT[off0] = lo + RES[off0];
            OUT[off1] = hi + RES[off1];
        }
    }
}

// ---------------------------------------------------------------------------
extern "C" void kernel_launch(void* const* d_in, const int* in_sizes, int n_in,
                              void* d_out, int out_size)
{
    const float* seq = (const float*)d_in[0];
    const float* M1  = (const float*)d_in[1];
    const float* P1  = (const float*)d_in[2];
    const float* g1  = (const float*)d_in[3];
    const float* b1  = (const float*)d_in[4];
    const float* M2  = (const float*)d_in[5];
    const float* P2  = (const float*)d_in[6];
    const float* g2  = (const float*)d_in[7];
    const float* b2  = (const float*)d_in[8];
    float* out = (float*)d_out;

    prep_mt_kernel <<<dim3(8, 8, 2), dim3(32, 8)>>>(M1, M2);
    prep_tbl_kernel<<<dim3(8, 8, 2), dim3(32, 8)>>>(P1, P2);

    // layer 1
    gemm_ln_kernel<<<ROWS / RT, 256>>>(seq, 0, g1, b1);
    phi_kernel<<<SEQ / GS, 256>>>(seq, nullptr, 0);

    // layer 2
    gemm_ln_kernel<<<ROWS / RT, 256>>>(nullptr, 1, g2, b2);
    phi_kernel<<<SEQ / GS, 256>>>(nullptr, out, 1);
}

// round 5
// speedup vs baseline: 1.3373x; 1.0560x over previous
#include <cuda_runtime.h>

#define D 256
#define BATCH 8
#define SEQ 1024
#define ROWS (BATCH*SEQ)
#define RT 32
#define GS 4            // positions per phi CTA

typedef unsigned long long ull;

// Scratch (static device globals -- no allocation allowed)
__device__ float  g_MT[2][D*D];        // M transposed: MT[k][i] = M[i][k]
__device__ float4 g_tbl[2][D*D];       // tbl[l][j*256+i] = (P[i][j], 1/p, 2cos(2pi/p), 0)
__device__ float  g_xt[ROWS*D];        // post GEMM+LN activations
__device__ float  g_y[ROWS*D];         // layer-1 output

// ---- f32x2 helpers (sm_103a packed fp32 pipe) ------------------------------
__device__ __forceinline__ ull pk2(float a, float b) {
    ull r; asm("mov.b64 %0, {%1,%2};" : "=l"(r) : "f"(a), "f"(b)); return r;
}
__device__ __forceinline__ void upk2(float& lo, float& hi, ull v) {
    asm("mov.b64 {%0,%1}, %2;" : "=f"(lo), "=f"(hi) : "l"(v));
}
__device__ __forceinline__ void fma2(ull& d, ull a, ull b) {
    asm("fma.rn.f32x2 %0, %1, %2, %0;" : "+l"(d) : "l"(a), "l"(b));
}

// ---------------------------------------------------------------------------
// Prep 1: transpose M1/M2 -> g_MT
// ---------------------------------------------------------------------------
__global__ void prep_mt_kernel(const float* __restrict__ M1, const float* __restrict__ M2)
{
    __shared__ float tile[32][33];
    const float* src = (blockIdx.z == 0) ? M1 : M2;
    float* dst = g_MT[blockIdx.z];

    int x = blockIdx.x * 32 + threadIdx.x;
    int y = blockIdx.y * 32 + threadIdx.y;
    #pragma unroll
    for (int r = 0; r < 32; r += 8)
        tile[threadIdx.y + r][threadIdx.x] = src[(y + r) * D + x];
    __syncthreads();
    x = blockIdx.y * 32 + threadIdx.x;
    y = blockIdx.x * 32 + threadIdx.y;
    #pragma unroll
    for (int r = 0; r < 32; r += 8)
        dst[(y + r) * D + x] = tile[threadIdx.x][threadIdx.y + r];
}

// ---------------------------------------------------------------------------
// Prep 2: fused table: g_tbl[l][j*256+i] = (P[i][j], 1/p, 2*cos(2*pi/p), 0)
// p = i*256 + j + 2
// ---------------------------------------------------------------------------
__global__ void prep_tbl_kernel(const float* __restrict__ P1, const float* __restrict__ P2)
{
    __shared__ float tile[32][33];
    const float* src = (blockIdx.z == 0) ? P1 : P2;
    float4* dst = g_tbl[blockIdx.z];

    int x = blockIdx.x * 32 + threadIdx.x;   // col j of P
    int y = blockIdx.y * 32 + threadIdx.y;   // row i of P
    #pragma unroll
    for (int r = 0; r < 32; r += 8)
        tile[threadIdx.y + r][threadIdx.x] = src[(y + r) * D + x];
    __syncthreads();
    int i = blockIdx.y * 32 + threadIdx.x;   // output col = i
    #pragma unroll
    for (int r = 0; r < 32; r += 8) {
        int j = blockIdx.x * 32 + threadIdx.y + r;
        float p    = (float)(i * D + j + 2);     // exact in fp32 (< 2^24)
        float rinv = 1.0f / p;
        float k2   = 2.0f * cospif(2.0f * rinv); // 2*cos(2*pi/p), ~1 ulp
        dst[(j << 8) + i] = make_float4(tile[threadIdx.x][threadIdx.y + r], rinv, k2, 0.f);
    }
}

// ---------------------------------------------------------------------------
// Kernel A: g_xt = LayerNorm(X @ M^T) * g + b     (f32x2 mainloop)
// grid = ROWS/RT, 256 threads (thread = output column i), RT rows per CTA
// ---------------------------------------------------------------------------
__global__ __launch_bounds__(256)
void gemm_ln_kernel(const float* __restrict__ Xext, int layer,
                    const float* __restrict__ gw, const float* __restrict__ bw)
{
    __shared__ float sm[256 * 36];

    const float* X  = (layer == 0) ? Xext : g_y;
    const float* MT = g_MT[layer];

    const int tid = threadIdx.x;
    const int r0  = blockIdx.x * RT;

    for (int idx = tid; idx < RT * D; idx += 256) {
        int r = idx >> 8, k = idx & 255;
        sm[k * 36 + r] = X[(r0 + r) * D + k];
    }
    __syncthreads();

    ull acc[16];
    #pragma unroll
    for (int q = 0; q < 16; q++) acc[q] = 0ULL;

    const int i = tid;
    #pragma unroll 4
    for (int k = 0; k < D; k++) {
        float m = __ldg(&MT[k * D + i]);                  // coalesced
        ull mm = pk2(m, m);
        const ulonglong2* xp = (const ulonglong2*)&sm[k * 36];   // broadcast
        #pragma unroll
        for (int q = 0; q < 8; q++) {
            ulonglong2 v = xp[q];
            fma2(acc[2 * q],     v.x, mm);
            fma2(acc[2 * q + 1], v.y, mm);
        }
    }
    __syncthreads();

    #pragma unroll
    for (int q = 0; q < 16; q++) {
        float lo, hi; upk2(lo, hi, acc[q]);
        sm[(2 * q) * D + i]     = lo;
        sm[(2 * q + 1) * D + i] = hi;
    }
    __syncthreads();

    const int w = tid >> 5, lane = tid & 31;
    for (int rr = w; rr < RT; rr += 8) {
        float s1 = 0.f, s2 = 0.f;
        float v[8];
        #pragma unroll
        for (int u = 0; u < 8; u++) {
            v[u] = sm[rr * D + u * 32 + lane];
            s1 += v[u];
            s2 = fmaf(v[u], v[u], s2);
        }
        #pragma unroll
        for (int o = 16; o > 0; o >>= 1) {
            s1 += __shfl_xor_sync(0xffffffffu, s1, o);
            s2 += __shfl_xor_sync(0xffffffffu, s2, o);
        }
        float mu   = s1 * (1.0f / D);
        float var  = s2 * (1.0f / D) - mu * mu;
        float rstd = rsqrtf(var + 1e-5f);
        int row = r0 + rr;
        #pragma unroll
        for (int u = 0; u < 8; u++) {
            int col = u * 32 + lane;
            g_xt[row * D + col] =
                (v[u] - mu) * rstd * __ldg(&gw[col]) + __ldg(&bw[col]);
        }
    }
}

// ---------------------------------------------------------------------------
// Kernel B: out[b,s,i] = res[b,s,i] + sum_j xt[b,s,j]*P[i,j]*cos(2*pi*s/p(i,j))
// grid = SEQ/GS CTAs, 256 threads (thread = dim i)
// cos over the GS positions via Chebyshev recurrence:
//   c(u+1) = k2*c(u) - c(u-1),  k2 = 2*cos(2*pi/p)   (from table)
// ---------------------------------------------------------------------------
__global__ __launch_bounds__(256, 2)
void phi_kernel(const float* __restrict__ resext, float* __restrict__ outext, int layer)
{
    __shared__ float xts[GS * D * 8];   // [u][j][b]  (32 KB)

    const float4* TB = g_tbl[layer];
    const float* RES = (layer == 0) ? resext : g_y;
    float* OUT       = (layer == 0) ? g_y    : outext;

    const int s0  = blockIdx.x * GS;
    const int tid = threadIdx.x;

    // stage GS*8 rows at positions s0..s0+GS-1, layout [u][j][b]
    for (int idx = tid; idx < GS * BATCH * D; idx += 256) {
        int row = idx >> 8;             // 0..31
        int j   = idx & 255;
        int b   = row >> 2;             // row = b*GS + u
        int u   = row & (GS - 1);
        xts[(u * D + j) * 8 + b] = g_xt[((b << 10) + s0 + u) * D + j];
    }
    __syncthreads();

    ull acc[GS][4];
    #pragma unroll
    for (int u = 0; u < GS; u++)
        #pragma unroll
        for (int q = 0; q < 4; q++) acc[u][q] = 0ULL;

    const float TWO_PI = 6.283185307179586f;
    const float sf0 = (float)s0;
    const float sf1 = (float)(s0 + 1);

    #pragma unroll 4
    for (int j = 0; j < D; j++) {
        float4 tb = __ldg(&TB[(j << 8) + tid]);   // (P, 1/p, 2cos(2pi/p)) coalesced
        // initial two cosines with exact-frac range reduction
        float t0 = sf0 * tb.y;  t0 -= floorf(t0);
        float t1 = sf1 * tb.y;  t1 -= floorf(t1);
        float c[GS];
        c[0] = __cosf(t0 * TWO_PI);
        c[1] = __cosf(t1 * TWO_PI);
        #pragma unroll
        for (int u = 2; u < GS; u++)
            c[u] = fmaf(tb.z, c[u - 1], -c[u - 2]);   // Chebyshev step

        #pragma unroll
        for (int u = 0; u < GS; u++) {
            float wv = c[u] * tb.x;
            ull wv2 = pk2(wv, wv);
            const ulonglong2* xb = (const ulonglong2*)&xts[(u * D + j) * 8]; // 32B aligned
            ulonglong2 x01 = xb[0];
            ulonglong2 x23 = xb[1];
            fma2(acc[u][0], x01.x, wv2);
            fma2(acc[u][1], x01.y, wv2);
            fma2(acc[u][2], x23.x, wv2);
            fma2(acc[u][3], x23.y, wv2);
        }
    }

    #pragma unroll
    for (int u = 0; u < GS; u++) {
        #pragma unroll
        for (int q = 0; q < 4; q++) {
            float lo, hi; upk2(lo, hi, acc[u][q]);
            int b0 = 2 * q;
            int off0 = ((b0 << 10)       + s0 + u) * D + tid;
            int off1 = (((b0 + 1) << 10) + s0 + u) * D + tid;
            OUT[off0] = lo + RES[off0];
            OUT[off1] = hi + RES[off1];
        }
    }
}

// ---------------------------------------------------------------------------
extern "C" void kernel_launch(void* const* d_in, const int* in_sizes, int n_in,
                              void* d_out, int out_size)
{
    const float* seq = (const float*)d_in[0];
    const float* M1  = (const float*)d_in[1];
    const float* P1  = (const float*)d_in[2];
    const float* g1  = (const float*)d_in[3];
    const float* b1  = (const float*)d_in[4];
    const float* M2  = (const float*)d_in[5];
    const float* P2  = (const float*)d_in[6];
    const float* g2  = (const float*)d_in[7];
    const float* b2  = (const float*)d_in[8];
    float* out = (float*)d_out;

    prep_mt_kernel <<<dim3(8, 8, 2), dim3(32, 8)>>>(M1, M2);
    prep_tbl_kernel<<<dim3(8, 8, 2), dim3(32, 8)>>>(P1, P2);

    // layer 1
    gemm_ln_kernel<<<ROWS / RT, 256>>>(seq, 0, g1, b1);
    phi_kernel<<<SEQ / GS, 256>>>(seq, nullptr, 0);

    // layer 2
    gemm_ln_kernel<<<ROWS / RT, 256>>>(nullptr, 1, g2, b2);
    phi_kernel<<<SEQ / GS, 256>>>(nullptr, out, 1);
}